// round 2
// baseline (speedup 1.0000x reference)
#include <cuda_runtime.h>

// Emformer layer, sm_103a. Round 2: fp32 SIMT, 4 kernels, lengths-dtype fix.
// T=1024 B=16 D=512 H=8 R=32 S=16 M=16  TQ=KL=1072, d_head=64, B*H=128.

#define TT    1024
#define BB    16
#define DD    512
#define HH    8
#define RR    32
#define SSUM  16
#define MMEM  16
#define TQL   1072
#define KLL   1072
#define DH    64
#define NH    128          // B*H
#define NEG_INF (-100000000.0f)
#define QSCALE  (0.125f)   // 64^-0.5

// Scratch (device globals: allocation-free rule)
__device__ float g_q   [(size_t)NH * TQL * DH];
__device__ float g_k   [(size_t)NH * KLL * DH];
__device__ float g_v   [(size_t)NH * KLL * DH];
__device__ float g_attn[(size_t)NH * TQL * DH];

// lengths may be int32 (JAX default, x64 disabled) or int64. Values are in
// [T/2, T] = [512,1024], all nonzero -> int64 layout has zero high words.
__device__ __forceinline__ int read_len(const void* lptr, int b) {
    const int* p32 = (const int*)lptr;
    const bool is64 = (p32[1] == 0) & (p32[3] == 0) & (p32[5] == 0);
    return is64 ? (int)(((const long long*)lptr)[b]) : p32[b];
}

// ---------------------------------------------------------------------------
// Q projection: g_q[b*H+h][t][dh] = ( gather_q(t,b,:) . Wq[h*64+dh,:] + bq ) * QSCALE
// gather_q: t<32 -> right_context[t], t<1056 -> utterance[t-32], else summary[t-1056]
// ---------------------------------------------------------------------------
__global__ void __launch_bounds__(256) proj_q_kernel(
    const float* __restrict__ utt, const float* __restrict__ rc,
    const float* __restrict__ summ, const float* __restrict__ W,
    const float* __restrict__ bias)
{
    __shared__ float AsT[32][68];
    __shared__ float Bs [32][68];
    const int t0 = blockIdx.x * 64;
    const int h  = blockIdx.y;
    const int b  = blockIdx.z;
    const int tid = threadIdx.x;
    const int tx = tid & 15, ty = tid >> 4;
    const int lr = tid >> 2, lc = tid & 3;

    const int t = t0 + lr;
    const float* arow = nullptr;
    if (t < RR)           arow = rc   + ((size_t)t * BB + b) * DD;
    else if (t < RR + TT) arow = utt  + ((size_t)(t - RR) * BB + b) * DD;
    else if (t < TQL)     arow = summ + ((size_t)(t - RR - TT) * BB + b) * DD;
    const float* wrow = W + (size_t)(h * 64 + lr) * DD;

    float acc[4][4];
#pragma unroll
    for (int i = 0; i < 4; i++)
#pragma unroll
        for (int j = 0; j < 4; j++) acc[i][j] = 0.f;

    for (int k0 = 0; k0 < DD; k0 += 32) {
        float4 a0, a1;
        if (arow) {
            a0 = *(const float4*)(arow + k0 + lc * 4);
            a1 = *(const float4*)(arow + k0 + 16 + lc * 4);
        } else { a0 = make_float4(0,0,0,0); a1 = a0; }
        float4 b0 = *(const float4*)(wrow + k0 + lc * 4);
        float4 b1 = *(const float4*)(wrow + k0 + 16 + lc * 4);
        __syncthreads();
        AsT[lc*4+0][lr]=a0.x; AsT[lc*4+1][lr]=a0.y; AsT[lc*4+2][lr]=a0.z; AsT[lc*4+3][lr]=a0.w;
        AsT[lc*4+16][lr]=a1.x; AsT[lc*4+17][lr]=a1.y; AsT[lc*4+18][lr]=a1.z; AsT[lc*4+19][lr]=a1.w;
        Bs [lc*4+0][lr]=b0.x; Bs [lc*4+1][lr]=b0.y; Bs [lc*4+2][lr]=b0.z; Bs [lc*4+3][lr]=b0.w;
        Bs [lc*4+16][lr]=b1.x; Bs [lc*4+17][lr]=b1.y; Bs [lc*4+18][lr]=b1.z; Bs [lc*4+19][lr]=b1.w;
        __syncthreads();
#pragma unroll
        for (int kk = 0; kk < 32; kk++) {
            float4 av = *(const float4*)(&AsT[kk][ty * 4]);
            float4 bv = *(const float4*)(&Bs [kk][tx * 4]);
            float aa[4] = {av.x, av.y, av.z, av.w};
            float bb[4] = {bv.x, bv.y, bv.z, bv.w};
#pragma unroll
            for (int i = 0; i < 4; i++)
#pragma unroll
                for (int j = 0; j < 4; j++) acc[i][j] += aa[i] * bb[j];
        }
    }
#pragma unroll
    for (int i = 0; i < 4; i++) {
        const int tt = t0 + ty * 4 + i;
        if (tt < TQL) {
            const int dh0 = tx * 4;
            float4 v;
            v.x = (acc[i][0] + bias[h*64+dh0+0]) * QSCALE;
            v.y = (acc[i][1] + bias[h*64+dh0+1]) * QSCALE;
            v.z = (acc[i][2] + bias[h*64+dh0+2]) * QSCALE;
            v.w = (acc[i][3] + bias[h*64+dh0+3]) * QSCALE;
            *(float4*)(g_q + (((size_t)(b*HH + h)) * TQL + tt) * DH + dh0) = v;
        }
    }
}

// ---------------------------------------------------------------------------
// KV projection: gather_kv: t<16 -> mems[t], t<48 -> rc[t-16], else utt[t-48]
// cb (blockIdx.y) 0..7 -> K head cb; 8..15 -> V head cb-8.
// ---------------------------------------------------------------------------
__global__ void __launch_bounds__(256) proj_kv_kernel(
    const float* __restrict__ mems, const float* __restrict__ rc,
    const float* __restrict__ utt, const float* __restrict__ W,
    const float* __restrict__ bias)
{
    __shared__ float AsT[32][68];
    __shared__ float Bs [32][68];
    const int t0 = blockIdx.x * 64;
    const int cb = blockIdx.y;          // 0..15
    const int b  = blockIdx.z;
    const int tid = threadIdx.x;
    const int tx = tid & 15, ty = tid >> 4;
    const int lr = tid >> 2, lc = tid & 3;

    const int t = t0 + lr;
    const float* arow = nullptr;
    if (t < MMEM)            arow = mems + ((size_t)t * BB + b) * DD;
    else if (t < MMEM + RR)  arow = rc   + ((size_t)(t - MMEM) * BB + b) * DD;
    else if (t < KLL)        arow = utt  + ((size_t)(t - MMEM - RR) * BB + b) * DD;
    const float* wrow = W + (size_t)(cb * 64 + lr) * DD;

    float acc[4][4];
#pragma unroll
    for (int i = 0; i < 4; i++)
#pragma unroll
        for (int j = 0; j < 4; j++) acc[i][j] = 0.f;

    for (int k0 = 0; k0 < DD; k0 += 32) {
        float4 a0, a1;
        if (arow) {
            a0 = *(const float4*)(arow + k0 + lc * 4);
            a1 = *(const float4*)(arow + k0 + 16 + lc * 4);
        } else { a0 = make_float4(0,0,0,0); a1 = a0; }
        float4 b0 = *(const float4*)(wrow + k0 + lc * 4);
        float4 b1 = *(const float4*)(wrow + k0 + 16 + lc * 4);
        __syncthreads();
        AsT[lc*4+0][lr]=a0.x; AsT[lc*4+1][lr]=a0.y; AsT[lc*4+2][lr]=a0.z; AsT[lc*4+3][lr]=a0.w;
        AsT[lc*4+16][lr]=a1.x; AsT[lc*4+17][lr]=a1.y; AsT[lc*4+18][lr]=a1.z; AsT[lc*4+19][lr]=a1.w;
        Bs [lc*4+0][lr]=b0.x; Bs [lc*4+1][lr]=b0.y; Bs [lc*4+2][lr]=b0.z; Bs [lc*4+3][lr]=b0.w;
        Bs [lc*4+16][lr]=b1.x; Bs [lc*4+17][lr]=b1.y; Bs [lc*4+18][lr]=b1.z; Bs [lc*4+19][lr]=b1.w;
        __syncthreads();
#pragma unroll
        for (int kk = 0; kk < 32; kk++) {
            float4 av = *(const float4*)(&AsT[kk][ty * 4]);
            float4 bv = *(const float4*)(&Bs [kk][tx * 4]);
            float aa[4] = {av.x, av.y, av.z, av.w};
            float bb[4] = {bv.x, bv.y, bv.z, bv.w};
#pragma unroll
            for (int i = 0; i < 4; i++)
#pragma unroll
                for (int j = 0; j < 4; j++) acc[i][j] += aa[i] * bb[j];
        }
    }
    float* dst = (cb < HH) ? g_k : g_v;
    const int h = cb & 7;
#pragma unroll
    for (int i = 0; i < 4; i++) {
        const int tt = t0 + ty * 4 + i;
        if (tt < KLL) {
            const int dh0 = tx * 4;
            float4 v;
            v.x = acc[i][0] + bias[cb*64+dh0+0];
            v.y = acc[i][1] + bias[cb*64+dh0+1];
            v.z = acc[i][2] + bias[cb*64+dh0+2];
            v.w = acc[i][3] + bias[cb*64+dh0+3];
            *(float4*)(dst + (((size_t)(b*HH + h)) * KLL + tt) * DH + dh0) = v;
        }
    }
}

// ---------------------------------------------------------------------------
// Flash attention: block = (q-tile 64, n). Online softmax, k-loop truncated by
// the near-causal mask (k <= q+M). Masks computed analytically.
// ---------------------------------------------------------------------------
#define FP 68
__global__ void __launch_bounds__(256) flash_kernel(const void* __restrict__ lengths)
{
    extern __shared__ float sm[];
    float* sQ = sm;                 // [64 d][FP] transposed: sQ[d*FP + q]
    float* sK = sm + 64 * FP;       // [64 d][FP] transposed: sK[d*FP + k]
    float* sV = sm + 2 * 64 * FP;   // [64 k][FP]            sV[k*FP + d]
    float* sP = sm + 3 * 64 * FP;   // [64 k][FP] transposed: sP[k*FP + q]

    const int qt = gridDim.x - 1 - blockIdx.x;   // heavy tiles launch first
    const int n  = blockIdx.y;
    const int b  = n >> 3;
    const int q0 = qt * 64;
    const int tid = threadIdx.x;
    const int tx = tid & 15, ty = tid >> 4;
    const int lr = tid >> 2, lc = tid & 3;

    int ml = read_len(lengths, 0);
#pragma unroll
    for (int i = 1; i < BB; i++) { int v = read_len(lengths, i); if (v > ml) ml = v; }
    const int klen = read_len(lengths, b) + MMEM + (TQL - ml - SSUM);

    // Q tile (transposed)
    {
        const int q = q0 + lr;
        const float* qrow = (q < TQL) ? (g_q + ((size_t)n * TQL + q) * DH) : nullptr;
#pragma unroll
        for (int c = 0; c < 4; c++) {
            const int c4 = (lc + 4 * c) * 4;
            float4 v = qrow ? *(const float4*)(qrow + c4) : make_float4(0,0,0,0);
            sQ[(c4+0)*FP + lr] = v.x; sQ[(c4+1)*FP + lr] = v.y;
            sQ[(c4+2)*FP + lr] = v.z; sQ[(c4+3)*FP + lr] = v.w;
        }
    }

    float m_i[4], l_i[4], o[4][4];
#pragma unroll
    for (int i = 0; i < 4; i++) {
        m_i[i] = NEG_INF; l_i[i] = 0.f;
#pragma unroll
        for (int j = 0; j < 4; j++) o[i][j] = 0.f;
    }

    const int nkt = min(17, qt + 2);   // k <= q+M truncation (M=16 < 64)
    for (int kt = 0; kt < nkt; kt++) {
        const int k0 = kt * 64;
        __syncthreads();
        {
            const int kk = k0 + lr;
            const bool ok = kk < KLL;
            const float* krow = g_k + ((size_t)n * KLL + (ok ? kk : 0)) * DH;
            const float* vrow = g_v + ((size_t)n * KLL + (ok ? kk : 0)) * DH;
#pragma unroll
            for (int c = 0; c < 4; c++) {
                const int c4 = (lc + 4 * c) * 4;
                float4 kv = ok ? *(const float4*)(krow + c4) : make_float4(0,0,0,0);
                float4 vv = ok ? *(const float4*)(vrow + c4) : make_float4(0,0,0,0);
                sK[(c4+0)*FP + lr] = kv.x; sK[(c4+1)*FP + lr] = kv.y;
                sK[(c4+2)*FP + lr] = kv.z; sK[(c4+3)*FP + lr] = kv.w;
                *(float4*)(sV + lr * FP + c4) = vv;
            }
        }
        __syncthreads();

        // S = Q K^T  (scaling pre-folded into Q)
        float s[4][4];
#pragma unroll
        for (int i = 0; i < 4; i++)
#pragma unroll
            for (int j = 0; j < 4; j++) s[i][j] = 0.f;
#pragma unroll 8
        for (int d = 0; d < DH; d++) {
            float4 av = *(const float4*)(sQ + d * FP + ty * 4);
            float4 bv = *(const float4*)(sK + d * FP + tx * 4);
            float aa[4] = {av.x, av.y, av.z, av.w};
            float bb[4] = {bv.x, bv.y, bv.z, bv.w};
#pragma unroll
            for (int i = 0; i < 4; i++)
#pragma unroll
                for (int j = 0; j < 4; j++) s[i][j] += aa[i] * bb[j];
        }

        // masks + online softmax (row groups = 16 contiguous lanes)
#pragma unroll
        for (int i = 0; i < 4; i++) {
            const int q = q0 + ty * 4 + i;
            float rmax = NEG_INF;
#pragma unroll
            for (int j = 0; j < 4; j++) {
                const int k = k0 + tx * 4 + j;
                const bool valid = (k <= q + MMEM) && (k < klen) && (k < KLL);
                s[i][j] = valid ? s[i][j] : NEG_INF;
                rmax = fmaxf(rmax, s[i][j]);
            }
#pragma unroll
            for (int off = 1; off < 16; off <<= 1)
                rmax = fmaxf(rmax, __shfl_xor_sync(0xffffffffu, rmax, off));
            const float mnew = fmaxf(m_i[i], rmax);
            const float corr = __expf(m_i[i] - mnew);
            m_i[i] = mnew;
            float rsum = 0.f;
#pragma unroll
            for (int j = 0; j < 4; j++) {
                const float p = __expf(s[i][j] - mnew);
                s[i][j] = p;
                rsum += p;
            }
#pragma unroll
            for (int off = 1; off < 16; off <<= 1)
                rsum += __shfl_xor_sync(0xffffffffu, rsum, off);
            l_i[i] = l_i[i] * corr + rsum;
#pragma unroll
            for (int j = 0; j < 4; j++) o[i][j] *= corr;
        }

        // P -> smem (transposed), then O += P V
#pragma unroll
        for (int j = 0; j < 4; j++)
#pragma unroll
            for (int i = 0; i < 4; i++)
                sP[(tx * 4 + j) * FP + ty * 4 + i] = s[i][j];
        __syncthreads();
#pragma unroll 8
        for (int k = 0; k < 64; k++) {
            float4 av = *(const float4*)(sP + k * FP + ty * 4);
            float4 bv = *(const float4*)(sV + k * FP + tx * 4);
            float aa[4] = {av.x, av.y, av.z, av.w};
            float bb[4] = {bv.x, bv.y, bv.z, bv.w};
#pragma unroll
            for (int i = 0; i < 4; i++)
#pragma unroll
                for (int j = 0; j < 4; j++) o[i][j] += aa[i] * bb[j];
        }
    }

#pragma unroll
    for (int i = 0; i < 4; i++) {
        const int q = q0 + ty * 4 + i;
        if (q < TQL) {
            const float inv = 1.f / l_i[i];
            float4 v;
            v.x = o[i][0] * inv; v.y = o[i][1] * inv;
            v.z = o[i][2] * inv; v.w = o[i][3] * inv;
            *(float4*)(g_attn + ((size_t)n * TQL + q) * DH + tx * 4) = v;
        }
    }
}

// ---------------------------------------------------------------------------
// Output projection + split/clip writeback.
// ---------------------------------------------------------------------------
__global__ void __launch_bounds__(256) out_proj_kernel(
    const float* __restrict__ W, const float* __restrict__ bias,
    float* __restrict__ out)
{
    __shared__ float AsT[32][68];
    __shared__ float Bs [32][68];
    const int t0 = blockIdx.x * 64;
    const int cb = blockIdx.y;
    const int b  = blockIdx.z;
    const int tid = threadIdx.x;
    const int tx = tid & 15, ty = tid >> 4;
    const int lr = tid >> 2, lc = tid & 3;
    const int t = t0 + lr;
    const float* wrow = W + (size_t)(cb * 64 + lr) * DD;

    float acc[4][4];
#pragma unroll
    for (int i = 0; i < 4; i++)
#pragma unroll
        for (int j = 0; j < 4; j++) acc[i][j] = 0.f;

    for (int k0 = 0; k0 < DD; k0 += 32) {
        float4 a0, a1;
        if (t < TQL) {
            const float* arow = g_attn +
                ((size_t)(b * HH + (k0 >> 6)) * TQL + t) * DH + (k0 & 63);
            a0 = *(const float4*)(arow + lc * 4);
            a1 = *(const float4*)(arow + 16 + lc * 4);
        } else { a0 = make_float4(0,0,0,0); a1 = a0; }
        float4 b0 = *(const float4*)(wrow + k0 + lc * 4);
        float4 b1 = *(const float4*)(wrow + k0 + 16 + lc * 4);
        __syncthreads();
        AsT[lc*4+0][lr]=a0.x; AsT[lc*4+1][lr]=a0.y; AsT[lc*4+2][lr]=a0.z; AsT[lc*4+3][lr]=a0.w;
        AsT[lc*4+16][lr]=a1.x; AsT[lc*4+17][lr]=a1.y; AsT[lc*4+18][lr]=a1.z; AsT[lc*4+19][lr]=a1.w;
        Bs [lc*4+0][lr]=b0.x; Bs [lc*4+1][lr]=b0.y; Bs [lc*4+2][lr]=b0.z; Bs [lc*4+3][lr]=b0.w;
        Bs [lc*4+16][lr]=b1.x; Bs [lc*4+17][lr]=b1.y; Bs [lc*4+18][lr]=b1.z; Bs [lc*4+19][lr]=b1.w;
        __syncthreads();
#pragma unroll
        for (int kk = 0; kk < 32; kk++) {
            float4 av = *(const float4*)(&AsT[kk][ty * 4]);
            float4 bv = *(const float4*)(&Bs [kk][tx * 4]);
            float aa[4] = {av.x, av.y, av.z, av.w};
            float bb[4] = {bv.x, bv.y, bv.z, bv.w};
#pragma unroll
            for (int i = 0; i < 4; i++)
#pragma unroll
                for (int j = 0; j < 4; j++) acc[i][j] += aa[i] * bb[j];
        }
    }

    const size_t mems_base = (size_t)(TQL - SSUM) * BB * DD;   // 1056*16*512
#pragma unroll
    for (int i = 0; i < 4; i++) {
        const int tt = t0 + ty * 4 + i;
        if (tt >= TQL - 1) continue;               // drop t=1071 (and padding)
        const int col = cb * 64 + tx * 4;
        float4 v;
        v.x = acc[i][0] + bias[col + 0];
        v.y = acc[i][1] + bias[col + 1];
        v.z = acc[i][2] + bias[col + 2];
        v.w = acc[i][3] + bias[col + 3];
        if (tt < TQL - SSUM) {
            *(float4*)(out + ((size_t)tt * BB + b) * DD + col) = v;
        } else {
            v.x = fminf(fmaxf(v.x, -10.f), 10.f);
            v.y = fminf(fmaxf(v.y, -10.f), 10.f);
            v.z = fminf(fmaxf(v.z, -10.f), 10.f);
            v.w = fminf(fmaxf(v.w, -10.f), 10.f);
            *(float4*)(out + mems_base +
                       ((size_t)(tt - (TQL - SSUM)) * BB + b) * DD + col) = v;
        }
    }
}

// ---------------------------------------------------------------------------
extern "C" void kernel_launch(void* const* d_in, const int* in_sizes, int n_in,
                              void* d_out, int out_size)
{
    const float* utt  = (const float*)d_in[0];
    const void*  len  = (const void*)d_in[1];   // int32 or int64, sniffed in-kernel
    const float* rc   = (const float*)d_in[2];
    const float* summ = (const float*)d_in[3];
    const float* mems = (const float*)d_in[4];
    // d_in[5] = attention_mask (deterministic; computed analytically in-kernel)
    const float* Wq   = (const float*)d_in[6];
    const float* bq   = (const float*)d_in[7];
    const float* Wkv  = (const float*)d_in[8];
    const float* bkv  = (const float*)d_in[9];
    const float* Wo   = (const float*)d_in[10];
    const float* bo   = (const float*)d_in[11];
    float* out = (float*)d_out;

    const int flash_smem = 4 * 64 * FP * (int)sizeof(float);   // 69632 B
    cudaFuncSetAttribute(flash_kernel,
                         cudaFuncAttributeMaxDynamicSharedMemorySize, flash_smem);

    proj_q_kernel  <<<dim3(17, 8, BB), 256>>>(utt, rc, summ, Wq, bq);
    proj_kv_kernel <<<dim3(17, 16, BB), 256>>>(mems, rc, utt, Wkv, bkv);
    flash_kernel   <<<dim3(17, NH), 256, flash_smem>>>(len);
    out_proj_kernel<<<dim3(17, 8, BB), 256>>>(Wo, bo, out);
}